// round 14
// baseline (speedup 1.0000x reference)
#include <cuda_runtime.h>
#include <cstdint>
#include <cstddef>

#define CC   64      // number of HMM states
#define TPB  256     // 4 threads (quad) per state
#define LOG2E_F 1.4426950408889634f
#define LN2_F   0.6931471805599453f
#define LNPI2_F 1.8378770664093453f        // ln(2*pi)
#define HALF_LN2PI_F 0.91893853320467267f  // f32(0.5*ln(2pi))

__device__ __forceinline__ float ex2f(float x){ float r; asm("ex2.approx.ftz.f32 %0, %1;" : "=f"(r) : "f"(x)); return r; }
__device__ __forceinline__ float lg2f(float x){ float r; asm("lg2.approx.ftz.f32 %0, %1;" : "=f"(r) : "f"(x)); return r; }
// sm_103a has INTEGER redux only (no redux.f32). f32 max via order-preserving u32 keys.
__device__ __forceinline__ unsigned redux_max_u32(unsigned v, unsigned mask){
    unsigned r; asm("redux.sync.max.u32 %0, %1, %2;" : "=r"(r) : "r"(v), "r"(mask)); return r;
}
__device__ __forceinline__ unsigned redux_min_u32(unsigned v, unsigned mask){
    unsigned r; asm("redux.sync.min.u32 %0, %1, %2;" : "=r"(r) : "r"(v), "r"(mask)); return r;
}
// monotonic bijection f32 -> u32 (total order, no NaNs in this path)
__device__ __forceinline__ unsigned f2key(float v){
    unsigned u = __float_as_uint(v);
    return (u & 0x80000000u) ? ~u : (u | 0x80000000u);
}
__device__ __forceinline__ float key2f(unsigned k){
    unsigned u = (k & 0x80000000u) ? (k ^ 0x80000000u) : ~k;
    return __uint_as_float(u);
}
__device__ __forceinline__ float grp_max_f32(float v, unsigned mask){
    return key2f(redux_max_u32(f2key(v), mask));
}

extern __shared__ unsigned char smem_raw[];

__global__ __launch_bounds__(TPB, 1)
void hmm_fv_kernel(const float* __restrict__ x,
                   const float* __restrict__ om,
                   const float* __restrict__ os,
                   const float* __restrict__ logA,
                   const float* __restrict__ logpi,
                   float* __restrict__ out,
                   int B, int T)
{
    // ---- shared layout (all float regions 16B aligned) ----
    float* fbase = (float*)smem_raw;
    float* pS0 = fbase;            // 64: forward P (buf 0), per-warp normalized
    float* pS1 = fbase + 64;       // 64
    float* dS0 = fbase + 128;      // 64: viterbi d (ln domain, unnormalized)
    float* dS1 = fbase + 192;      // 64
    float* sx0 = fbase + 256;      // 8: per-warp a2 maxima (buf 0)
    float* sx1 = fbase + 264;      // 8
    unsigned char* cbuf = (unsigned char*)(fbase + 272);        // T bytes (padded)
    unsigned char* psiS = cbuf + ((T + 15) & ~15);              // T*CC bytes
    // preamble staging inside psi region (psi rows written only at t>=1, after constants read)
    float* stage = (float*)psiS;             // CC*CC: raw logA
    float* rowM  = stage + CC*CC;            // CC: row max
    float* rowL  = rowM + CC;                // CC: row log-sum-exp

    const int tid = threadIdx.x;
    const int b   = blockIdx.x;
    const int c   = tid >> 2;     // state
    const int q   = tid & 3;      // quad slice: 16 predecessors + emission dim q
    const unsigned qmask = 0xFu << (tid & 0x1C);   // this quad's lanes within the warp

    // ================= preamble =================
    for (int idx = tid; idx < CC*CC; idx += TPB) stage[idx] = logA[idx];
    if (tid < CC) pS0[tid] = logpi[tid];
    __syncthreads();

    if (tid < CC) {   // ref-exact row log-softmax pieces
        const float* row = stage + tid*CC;
        float m = row[0];
        for (int j = 1; j < CC; j++) m = fmaxf(m, row[j]);
        float s = 0.f;
        for (int j = 0; j < CC; j++) s = __fadd_rn(s, expf(__fsub_rn(row[j], m)));
        rowM[tid] = m;
        rowL[tid] = logf(s);
    }
    __syncthreads();

    // transition constants: predecessors i = q*16 + j -> state c
    float LAln[16], Ac[16];
    #pragma unroll
    for (int j = 0; j < 16; j++) {
        int gi = q*16 + j;
        float la = __fsub_rn(__fsub_rn(stage[gi*CC + c], rowM[gi]), rowL[gi]);
        LAln[j] = la;
        Ac[j]   = expf(la);
    }

    // normalized log pi (ref-exact ln) + log2 version
    float lpiln, lpi2;
    {
        float m = pS0[0];
        for (int j = 1; j < CC; j++) m = fmaxf(m, pS0[j]);
        float s = 0.f;
        for (int j = 0; j < CC; j++) s = __fadd_rn(s, expf(__fsub_rn(pS0[j], m)));
        float lse = logf(s);
        lpiln = __fsub_rn(__fsub_rn(pS0[c], m), lse);
        lpi2  = lpiln * LOG2E_F;
    }

    // per-lane emission constants (dim q of state c)
    float muq = om[c*6 + q];
    float sgq = fmaxf(os[c*6 + q], 0.f) + 0.1f;
    float lsgq = logf(sgq);                        // ref-exact log(sigma)
    const float rconst = 0.84932180028801905f;     // sqrt(0.5*log2 e)
    float eaq = rconst / sgq;
    float ebq = -muq * eaq;
    float K;
    {   // K = -4*0.5*ln(2pi)*log2e - sum_d log2(sd)   (forward, loose)
        float kp = lg2f(sgq);
        kp += __shfl_xor_sync(0xFFFFFFFFu, kp, 1);
        kp += __shfl_xor_sync(0xFFFFFFFFu, kp, 2);
        K = -2.0f * LNPI2_F * LOG2E_F - kp;
    }
    __syncthreads();   // readers of stage/rowM/rowL/pS0 done before overwrite

    const float* xb = x + (size_t)b * (size_t)T * 6;
    float M2 = 0.f;    // accumulates global shifts; first addition at t=1

    // ---- t = 0: per-warp normalized init, ONE bar ----
    {
        float xq = __ldg(xb + q);
        float z  = __fdiv_rn(__fsub_rn(xq, muq), sgq);
        float tq = __fsub_rn(__fsub_rn(__fmul_rn(__fmul_rn(-0.5f, z), z), lsgq), HALF_LN2PI_F);
        float yq = fmaf(xq, eaq, ebq);
        float y2 = yq * yq;

        float b1 = __shfl_xor_sync(0xFFFFFFFFu, tq, 1);
        float c2 = __shfl_xor_sync(0xFFFFFFFFu, tq, 2);
        float c3 = __shfl_xor_sync(0xFFFFFFFFu, b1, 2);
        float lpln = __fadd_rn(__fadd_rn(__fadd_rn(tq, b1), c2), c3);  // ref order on q==0

        float sy2 = y2 + __shfl_xor_sync(0xFFFFFFFFu, y2, 1);
        sy2 += __shfl_xor_sync(0xFFFFFFFFu, sy2, 2);
        float lp2 = K - sy2;

        float a2 = lp2 + lpi2;
        float d0 = __fadd_rn(lpln, lpiln);   // ref: logp + log_pi

        float wm = grp_max_f32(a2, 0xFFFFFFFFu);   // warp max (8 states/warp)

        if ((tid & 31) == 0) sx0[tid >> 5] = wm;
        if (q == 0) { pS0[c] = ex2f(a2 - wm); dS0[c] = d0; }   // per-warp normalized
        __syncthreads();
    }

    // ---- main loop: ONE __syncthreads per step, double-buffered ----
    float *pR = pS0, *pW = pS1, *dR = dS0, *dW = dS1, *sxR = sx0, *sxW = sx1;
    unsigned char* psp = psiS + CC;
    const float* xp = xb + 6 + q;
    float xq = __ldg(xp);

    for (int t = 1; t < T; t++) {
        // prefetch x for t+1 (clamped)
        const float* xpn = (t + 1 < T) ? (xp + 6) : xp;
        float xqn = __ldg(xpn);

        // previous step's per-warp maxima -> global max m2 + this lane's 2 group factors
        float4 s0 = *(const float4*)sxR, s1 = *((const float4*)sxR + 1);
        float m2 = fmaxf(fmaxf(fmaxf(s0.x,s0.y),fmaxf(s0.z,s0.w)),
                         fmaxf(fmaxf(s1.x,s1.y),fmaxf(s1.z,s1.w)));
        M2 += m2;
        float wa, wb;   // maxima of source warps 2q and 2q+1
        if      (q == 0) { wa = s0.x; wb = s0.y; }
        else if (q == 1) { wa = s0.z; wb = s0.w; }
        else if (q == 2) { wa = s1.x; wb = s1.y; }
        else             { wa = s1.z; wb = s1.w; }
        float fA = ex2f(wa - m2);
        float fB = ex2f(wb - m2);

        // emission (per-lane, 1 div)
        float z  = __fdiv_rn(__fsub_rn(xq, muq), sgq);
        float tq = __fsub_rn(__fsub_rn(__fmul_rn(__fmul_rn(-0.5f, z), z), lsgq), HALF_LN2PI_F);
        float yq = fmaf(xq, eaq, ebq);
        float y2 = yq * yq;

        float bb1 = __shfl_xor_sync(0xFFFFFFFFu, tq, 1);
        float cc2 = __shfl_xor_sync(0xFFFFFFFFu, tq, 2);
        float cc3 = __shfl_xor_sync(0xFFFFFFFFu, bb1, 2);
        float lpln = __fadd_rn(__fadd_rn(__fadd_rn(tq, bb1), cc2), cc3);  // ref-order on q==0

        float sy2 = y2 + __shfl_xor_sync(0xFFFFFFFFu, y2, 1);
        sy2 += __shfl_xor_sync(0xFFFFFFFFu, sy2, 2);
        float lp2 = K - sy2;

        // ---- forward dot (split by source warp) + viterbi scores (no pred chain) ----
        const float4* p4 = (const float4*)pR + q*4;
        const float4* d4 = (const float4*)dR + q*4;
        float dA0 = 0.f, dA1 = 0.f, dB0 = 0.f, dB1 = 0.f;
        float w[16];
        #pragma unroll
        for (int j = 0; j < 2; j++) {        // predecessors from warp 2q
            float4 pv = p4[j];
            dA0 = fmaf(pv.x, Ac[j*4+0], dA0);
            dA1 = fmaf(pv.y, Ac[j*4+1], dA1);
            dA0 = fmaf(pv.z, Ac[j*4+2], dA0);
            dA1 = fmaf(pv.w, Ac[j*4+3], dA1);
            float4 dv = d4[j];
            w[j*4+0] = __fadd_rn(dv.x, LAln[j*4+0]);
            w[j*4+1] = __fadd_rn(dv.y, LAln[j*4+1]);
            w[j*4+2] = __fadd_rn(dv.z, LAln[j*4+2]);
            w[j*4+3] = __fadd_rn(dv.w, LAln[j*4+3]);
        }
        #pragma unroll
        for (int j = 2; j < 4; j++) {        // predecessors from warp 2q+1
            float4 pv = p4[j];
            dB0 = fmaf(pv.x, Ac[j*4+0], dB0);
            dB1 = fmaf(pv.y, Ac[j*4+1], dB1);
            dB0 = fmaf(pv.z, Ac[j*4+2], dB0);
            dB1 = fmaf(pv.w, Ac[j*4+3], dB1);
            float4 dv = d4[j];
            w[j*4+0] = __fadd_rn(dv.x, LAln[j*4+0]);
            w[j*4+1] = __fadd_rn(dv.y, LAln[j*4+1]);
            w[j*4+2] = __fadd_rn(dv.z, LAln[j*4+2]);
            w[j*4+3] = __fadd_rn(dv.w, LAln[j*4+3]);
        }
        float dot = fmaf(fA, dA0 + dA1, fB * (dB0 + dB1));

        // within-lane argmax: fmax tree + parallel equality mask + ffs (first-max-wins)
        float v01 = fmaxf(w[0], w[1]),   v23 = fmaxf(w[2], w[3]);
        float v45 = fmaxf(w[4], w[5]),   v67 = fmaxf(w[6], w[7]);
        float v89 = fmaxf(w[8], w[9]),   vab = fmaxf(w[10], w[11]);
        float vcd = fmaxf(w[12], w[13]), vef = fmaxf(w[14], w[15]);
        float v03 = fmaxf(v01, v23), v47 = fmaxf(v45, v67);
        float v8b = fmaxf(v89, vab), vcf = fmaxf(vcd, vef);
        float best = fmaxf(fmaxf(v03, v47), fmaxf(v8b, vcf));
        unsigned msk = 0u;
        #pragma unroll
        for (int j = 0; j < 16; j++) msk |= (w[j] == best) ? (1u << j) : 0u;
        unsigned barg = (unsigned)(q*16) + (unsigned)(__ffs(msk) - 1);

        // quad reductions: dot sum (2 shfl), best max (1 redux via keys), tie-break (1 redux)
        dot += __shfl_xor_sync(0xFFFFFFFFu, dot, 1);
        dot += __shfl_xor_sync(0xFFFFFFFFu, dot, 2);
        float gbest = grp_max_f32(best, qmask);
        unsigned cand = (best == gbest) ? barg : 255u;
        cand = redux_min_u32(cand, qmask);

        float a2 = lp2 + lg2f(dot);

        float wm = grp_max_f32(a2, 0xFFFFFFFFu);   // warp max, one redux

        float Pn = ex2f(a2 - wm);                 // per-warp normalization: never all-flush
        float dn = __fadd_rn(gbest, lpln);        // ref-exact, unnormalized

        if ((tid & 31) == 0) sxW[tid >> 5] = wm;
        if (q == 0) {
            pW[c] = Pn;
            dW[c] = dn;
            psp[c] = (unsigned char)cand;
        }
        psp += CC; xq = xqn; xp = xpn;

        float* tf;
        tf = pR;  pR  = pW;  pW  = tf;
        tf = dR;  dR  = dW;  dW  = tf;
        tf = sxR; sxR = sxW; sxW = tf;

        __syncthreads();
    }

    // ---- finalize: logp_x + viterbi backtrack (last written = pR/dR/sxR) ----
    if (tid == 0) {
        float m2l = sxR[0];
        for (int w8 = 1; w8 < 8; w8++) m2l = fmaxf(m2l, sxR[w8]);
        float s = 0.f;
        for (int w8 = 0; w8 < 8; w8++) {
            float sub = 0.f;
            for (int k = 0; k < 8; k++) sub += pR[w8*8 + k];
            s += ex2f(sxR[w8] - m2l) * sub;
        }
        out[b] = LN2_F * (M2 + m2l + lg2f(s));

        float bd = dR[0]; int cl = 0;
        for (int j = 1; j < CC; j++) { float v = dR[j]; if (v > bd) { bd = v; cl = j; } }
        int cc = cl;
        cbuf[T-1] = (unsigned char)cc;
        for (int t = T - 1; t >= 1; t--) {
            cc = psiS[t*CC + cc];
            cbuf[t-1] = (unsigned char)cc;
        }
    }
    __syncthreads();

    float* outc = out + B;
    for (int idx = tid; idx < T; idx += TPB)
        outc[(size_t)b * T + idx] = (float)cbuf[idx];
}

extern "C" void kernel_launch(void* const* d_in, const int* in_sizes, int n_in,
                              void* d_out, int out_size)
{
    const float* x    = (const float*)d_in[0];
    const float* om   = (const float*)d_in[1];
    const float* os   = (const float*)d_in[2];
    const float* lA   = (const float*)d_in[3];
    const float* lpi  = (const float*)d_in[4];

    int B = out_size - in_sizes[0] / 6;
    int T = in_sizes[0] / (6 * B);

    size_t smemsz = (size_t)272 * sizeof(float)        // pS0/1, dS0/1, sx0/1
                  + (size_t)((T + 15) & ~15)           // cbuf
                  + (size_t)T * CC;                    // psi
    size_t stage_need = (size_t)272 * sizeof(float) + (size_t)((T + 15) & ~15)
                      + (size_t)(CC*CC + 2*CC) * sizeof(float);
    if (stage_need > smemsz) smemsz = stage_need;

    cudaFuncSetAttribute(hmm_fv_kernel,
                         cudaFuncAttributeMaxDynamicSharedMemorySize,
                         (int)smemsz);

    hmm_fv_kernel<<<B, TPB, smemsz>>>(x, om, os, lA, lpi, (float*)d_out, B, T);
}